// round 12
// baseline (speedup 1.0000x reference)
#include <cuda_runtime.h>
#include <cstdint>
#include <cstddef>

#define Bq 32
#define Sq 100
#define Tq 100
#define Eq 512
#define Hq 512
#define G4 2048   // 4H
#define H2 1024   // 2H
#define H3 1536   // 3H
#define VTq 32000

// ---------------- scratch (static device globals; no allocation) ----------------
__device__ float g_xsrc[Sq * Bq * Eq];            // gathered source embeddings [S,B,E]
__device__ float g_Xf[Sq * Bq * G4];              // fwd enc input gates [S,B,4H]
__device__ float g_Xb[Sq * Bq * G4];              // bwd enc input gates [S,B,4H]
__device__ float g_henc[2][2][Bq][Hq];            // [slot][dir][b][h] ping-pong
__device__ float g_cenc[2][Bq][Hq];               // [dir][b][h]
__device__ float g_encout[Bq][Sq][H2];            // [B,S,2H]
__device__ float g_encT[Bq][H2][Sq];              // transposed for ctx reduction
__device__ float g_P[(size_t)Bq * Sq * H3];       // precomputed att layer1 (enc part)
__device__ float g_temb[Bq][Tq][Eq];
__device__ float g_temb_tb[Tq * Bq * Eq];         // [T,B,E]
__device__ float g_Xdec[Tq * Bq * G4];            // dec input gates (emb part) [T,B,4H]
__device__ float g_hdec[2][Bq][Hq];
__device__ float g_cdec[Bq][Hq];
__device__ float g_Qpart[16][Bq][H3];             // k-split partials of Q projection
__device__ float g_ctxs[Tq][Bq][H2];
__device__ float g_decs[Tq][Bq][Hq];
__device__ float g_clsin[(size_t)Bq * Tq * 2048];
__device__ float g_hid[(size_t)Bq * Tq * H2];

__device__ __forceinline__ float sigf(float x) { return 1.f / (1.f + __expf(-x)); }

__device__ __forceinline__ uint32_t f2tf(float x) {
    uint32_t r;
    asm("cvt.rna.tf32.f32 %0, %1;" : "=r"(r) : "f"(x));
    return r;
}

// ---------------- init ----------------
__global__ void k_zero_state() {
    int i = blockIdx.x * 256 + threadIdx.x;
    if (i < 2 * 2 * Bq * Hq) ((float*)g_henc)[i] = 0.f;
    if (i < 2 * Bq * Hq)     ((float*)g_cenc)[i] = 0.f;
}

__global__ void k_gather_src(const int* __restrict__ src, const float* __restrict__ emb) {
    int m = blockIdx.x;            // m = s*B + b
    int s = m / Bq, b = m % Bq;
    int idx = src[b * Sq + s];
    float4 v = ((const float4*)(emb + (size_t)idx * Eq))[threadIdx.x];
    ((float4*)(g_xsrc + (size_t)m * Eq))[threadIdx.x] = v;
}

__global__ void k_gather_tgt(const int* __restrict__ tgt, const float* __restrict__ emb) {
    int m = blockIdx.x;            // m = b*T + t
    int b = m / Tq, t = m % Tq;
    int idx = tgt[m];
    float4 v = ((const float4*)(emb + (size_t)idx * Eq))[threadIdx.x];
    ((float4*)(&g_temb[b][t][0]))[threadIdx.x] = v;
    ((float4*)(g_temb_tb + ((size_t)t * Bq + b) * Eq))[threadIdx.x] = v;
}

// ---------------- tf32 tensor-core GEMM ----------------
// C[M,N] = act(A[M,K] @ W[N,K]^T + bias1 (+bias2))
// block tile 128x128, BK=16, 256 threads = 8 warps (2 M x 4 N), warp tile 64x32.
// grid: (M/128, N/128) -- bm fastest so consecutive blocks share the W tile (L2 reuse).
#define SSTR 20   // shared stride in floats; conflict-free for fragment pattern
__global__ void __launch_bounds__(256) k_mma(
    const float* __restrict__ A, int lda,
    const float* __restrict__ W, int ldw,
    const float* __restrict__ bias1, const float* __restrict__ bias2,
    float* __restrict__ C, int ldc,
    int M, int N, int K, int do_relu)
{
    __shared__ uint32_t As[128 * SSTR];
    __shared__ uint32_t Ws[128 * SSTR];
    int tid = threadIdx.x;
    int bm = blockIdx.x * 128, bn = blockIdx.y * 128;

    int warp = tid >> 5, lane = tid & 31;
    int wm = warp & 1, wn = warp >> 1;           // warp tile: rows wm*64, cols wn*32
    int grp = lane >> 2, qid = lane & 3;

    // loader mapping: 512 float4 per tile (A) : idx -> row=idx>>2, quad=idx&3
    int l_row = (tid * 2) >> 2;                  // rows for i=0 ; i=1 adds 128
    int l_q0 = (tid * 2) & 3;

    float acc[4][4][4];
#pragma unroll
    for (int i = 0; i < 4; i++)
#pragma unroll
        for (int j = 0; j < 4; j++)
#pragma unroll
            for (int r = 0; r < 4; r++) acc[i][j][r] = 0.f;

    for (int k0 = 0; k0 < K; k0 += 16) {
        // load A tile 128x16 and W tile 128x16, convert to tf32, store swizzle-free
#pragma unroll
        for (int i = 0; i < 2; i++) {
            int idx = tid * 2 + i;               // 0..511
            int row = idx >> 2, q = idx & 3;
            float4 av = *(const float4*)(A + (size_t)(bm + row) * lda + k0 + q * 4);
            float4 wv = *(const float4*)(W + (size_t)(bn + row) * ldw + k0 + q * 4);
            uint4 at = make_uint4(f2tf(av.x), f2tf(av.y), f2tf(av.z), f2tf(av.w));
            uint4 wt = make_uint4(f2tf(wv.x), f2tf(wv.y), f2tf(wv.z), f2tf(wv.w));
            *(uint4*)&As[row * SSTR + q * 4] = at;
            *(uint4*)&Ws[row * SSTR + q * 4] = wt;
        }
        __syncthreads();
#pragma unroll
        for (int kf = 0; kf < 2; kf++) {
            int kb = kf * 8;
            uint32_t a[4][4], b[4][2];
#pragma unroll
            for (int mf = 0; mf < 4; mf++) {
                int rb = (wm * 64 + mf * 16) * SSTR + kb;
                a[mf][0] = As[rb + grp * SSTR + qid];
                a[mf][1] = As[rb + (grp + 8) * SSTR + qid];
                a[mf][2] = As[rb + grp * SSTR + qid + 4];
                a[mf][3] = As[rb + (grp + 8) * SSTR + qid + 4];
            }
#pragma unroll
            for (int nf = 0; nf < 4; nf++) {
                int cb = (wn * 32 + nf * 8 + grp) * SSTR + kb;
                b[nf][0] = Ws[cb + qid];
                b[nf][1] = Ws[cb + qid + 4];
            }
#pragma unroll
            for (int mf = 0; mf < 4; mf++)
#pragma unroll
                for (int nf = 0; nf < 4; nf++) {
                    asm volatile(
                        "mma.sync.aligned.m16n8k8.row.col.f32.tf32.tf32.f32 "
                        "{%0,%1,%2,%3}, {%4,%5,%6,%7}, {%8,%9}, {%0,%1,%2,%3};\n"
                        : "+f"(acc[mf][nf][0]), "+f"(acc[mf][nf][1]),
                          "+f"(acc[mf][nf][2]), "+f"(acc[mf][nf][3])
                        : "r"(a[mf][0]), "r"(a[mf][1]), "r"(a[mf][2]), "r"(a[mf][3]),
                          "r"(b[nf][0]), "r"(b[nf][1]));
                }
        }
        __syncthreads();
    }

    // epilogue
#pragma unroll
    for (int nf = 0; nf < 4; nf++) {
        int col = bn + wn * 32 + nf * 8 + qid * 2;
        float b0 = bias1[col], b1 = bias1[col + 1];
        if (bias2) { b0 += bias2[col]; b1 += bias2[col + 1]; }
#pragma unroll
        for (int mf = 0; mf < 4; mf++) {
            int row = bm + wm * 64 + mf * 16 + grp;
            float v0 = acc[mf][nf][0] + b0, v1 = acc[mf][nf][1] + b1;
            float v2 = acc[mf][nf][2] + b0, v3 = acc[mf][nf][3] + b1;
            if (do_relu) {
                v0 = fmaxf(v0, 0.f); v1 = fmaxf(v1, 0.f);
                v2 = fmaxf(v2, 0.f); v3 = fmaxf(v3, 0.f);
            }
            *(float2*)&C[(size_t)row * ldc + col] = make_float2(v0, v1);
            *(float2*)&C[(size_t)(row + 8) * ldc + col] = make_float2(v2, v3);
        }
    }
}

// ---------------- fused encoder step (both directions) ----------------
__global__ void __launch_bounds__(128) k_enc_step(int s,
    const float* __restrict__ Whh_f, const float* __restrict__ Whh_b)
{
    __shared__ float hs[Hq];
    __shared__ float gv[128];
    int chunk = blockIdx.x, b = blockIdx.y, d = blockIdx.z;
    int tid = threadIdx.x;
    int slot = s & 1;
    ((float4*)hs)[tid] = ((const float4*)&g_henc[slot][d][b][0])[tid];
    __syncthreads();
    int gate = tid >> 5, lane = tid & 31;
    int unit = chunk * 32 + lane;
    int grow = gate * Hq + unit;
    int seff = d ? (Sq - 1 - s) : s;
    const float* X = d ? g_Xb : g_Xf;
    const float* W = (d ? Whh_b : Whh_f) + (size_t)grow * Hq;
    float acc = X[((size_t)seff * Bq + b) * G4 + grow];
    const float4* W4 = (const float4*)W;
    const float4* h4 = (const float4*)hs;
#pragma unroll 8
    for (int k = 0; k < 128; k++) {
        float4 w = W4[k], h = h4[k];
        acc += w.x * h.x + w.y * h.y + w.z * h.z + w.w * h.w;
    }
    gv[tid] = acc;
    __syncthreads();
    if (tid < 32) {
        int u = chunk * 32 + tid;
        float iv = sigf(gv[tid]);
        float fv = sigf(gv[32 + tid]);
        float gg = tanhf(gv[64 + tid]);
        float ov = sigf(gv[96 + tid]);
        float c = g_cenc[d][b][u];
        c = fv * c + iv * gg;
        float h = ov * tanhf(c);
        g_cenc[d][b][u] = c;
        g_henc[slot ^ 1][d][b][u] = h;
        g_encout[b][seff][d * Hq + u] = h;
        g_encT[b][d * Hq + u][seff] = h;
    }
}

__global__ void k_dec_init() {
    int i = blockIdx.x * 256 + threadIdx.x;
    if (i < Bq * Hq) {
        ((float*)g_hdec)[i] = ((const float*)g_henc)[i];  // slot0, dir0 = final fwd h
        ((float*)g_cdec)[i] = ((const float*)g_cenc)[i];  // dir0 = final fwd c
    }
}

// ---------------- decoder: Q projection, k-split ----------------
__global__ void __launch_bounds__(256) k_qproj(int t, const float* __restrict__ att1_W) {
    __shared__ float hs[32][33];
    int tid = threadIdx.x;
    int jc = blockIdx.x, ks = blockIdx.y;
    int k0 = ks * 32;
    int slot = t & 1;
    {
        int b = tid >> 3, kk = (tid & 7) * 4;
        float4 v = *(const float4*)&g_hdec[slot][b][k0 + kk];
        hs[b][kk] = v.x; hs[b][kk + 1] = v.y; hs[b][kk + 2] = v.z; hs[b][kk + 3] = v.w;
    }
    __syncthreads();
    int j = jc * 128 + (tid & 127);
    int b0 = (tid >> 7) * 16;
    const float4* Wr = (const float4*)(att1_W + (size_t)j * H3 + H2 + k0);
    float acc[16];
#pragma unroll
    for (int b = 0; b < 16; b++) acc[b] = 0.f;
#pragma unroll
    for (int kg = 0; kg < 8; kg++) {
        float4 w = Wr[kg];
#pragma unroll
        for (int b = 0; b < 16; b++) {
            acc[b] += w.x * hs[b0 + b][kg * 4] + w.y * hs[b0 + b][kg * 4 + 1]
                    + w.z * hs[b0 + b][kg * 4 + 2] + w.w * hs[b0 + b][kg * 4 + 3];
        }
    }
#pragma unroll
    for (int b = 0; b < 16; b++) g_Qpart[ks][b0 + b][j] = acc[b];
}

// ---------------- decoder: scores + softmax + context ----------------
__global__ void __launch_bounds__(512) k_attn(int t, const float* __restrict__ att2_W) {
    __shared__ float Qs[H3];
    __shared__ float a2[H3];
    __shared__ float wsm[128];
    int b = blockIdx.x, tid = threadIdx.x;
    for (int j = tid; j < H3; j += 512) {
        a2[j] = att2_W[j];
        float q = 0.f;
#pragma unroll
        for (int p = 0; p < 16; p++) q += g_Qpart[p][b][j];
        Qs[j] = q;
    }
    __syncthreads();
    int warp = tid >> 5, lane = tid & 31;
    for (int s = warp; s < Sq; s += 16) {
        const float* Pp = g_P + ((size_t)b * Sq + s) * H3;
        float acc = 0.f;
        for (int j = lane; j < H3; j += 32) {
            float v = Pp[j] + Qs[j];
            acc += fmaxf(v, 0.f) * a2[j];
        }
#pragma unroll
        for (int o = 16; o; o >>= 1) acc += __shfl_xor_sync(0xffffffffu, acc, o);
        if (!lane) wsm[s] = acc;
    }
    __syncthreads();
    if (tid < 32) {
        float m = -1e30f;
        for (int s = tid; s < Sq; s += 32) m = fmaxf(m, wsm[s]);
#pragma unroll
        for (int o = 16; o; o >>= 1) m = fmaxf(m, __shfl_xor_sync(0xffffffffu, m, o));
        float e[4];
        float sum = 0.f;
        int i = 0;
        for (int s = tid; s < Sq; s += 32, i++) { e[i] = __expf(wsm[s] - m); sum += e[i]; }
#pragma unroll
        for (int o = 16; o; o >>= 1) sum += __shfl_xor_sync(0xffffffffu, sum, o);
        float inv = 1.f / sum;
        i = 0;
        for (int s = tid; s < Sq; s += 32, i++) wsm[s] = e[i] * inv;
    }
    __syncthreads();
    for (int k = tid; k < H2; k += 512) {
        const float* eT = &g_encT[b][k][0];
        float acc = 0.f;
#pragma unroll 4
        for (int s = 0; s < Sq; s++) acc += wsm[s] * eT[s];
        g_ctxs[t][b][k] = acc;
    }
}

// ---------------- decoder: fused LSTM gates + state update ----------------
__global__ void __launch_bounds__(128) k_dec_lstm(int t,
    const float* __restrict__ Wih, const float* __restrict__ Whh)
{
    __shared__ float xs[H2 + Hq];   // ctx (1024) then h (512)
    __shared__ float gv[128];
    int chunk = blockIdx.x, b = blockIdx.y, tid = threadIdx.x;
    int slot = t & 1;
    {
        const float4* c4 = (const float4*)&g_ctxs[t][b][0];
        float4* s4 = (float4*)xs;
        s4[tid] = c4[tid];
        s4[128 + tid] = c4[128 + tid];
        s4[256 + tid] = ((const float4*)&g_hdec[slot][b][0])[tid];
    }
    __syncthreads();
    int gate = tid >> 5, lane = tid & 31;
    int unit = chunk * 32 + lane;
    int grow = gate * Hq + unit;
    float acc = g_Xdec[((size_t)t * Bq + b) * G4 + grow];
    const float4* Wi4 = (const float4*)(Wih + (size_t)grow * H3 + Eq);
    const float4* x4 = (const float4*)xs;
#pragma unroll 8
    for (int k = 0; k < 256; k++) {
        float4 w = Wi4[k], x = x4[k];
        acc += w.x * x.x + w.y * x.y + w.z * x.z + w.w * x.w;
    }
    const float4* Wh4 = (const float4*)(Whh + (size_t)grow * Hq);
#pragma unroll 8
    for (int k = 0; k < 128; k++) {
        float4 w = Wh4[k], x = x4[256 + k];
        acc += w.x * x.x + w.y * x.y + w.z * x.z + w.w * x.w;
    }
    gv[tid] = acc;
    __syncthreads();
    if (tid < 32) {
        int u = chunk * 32 + tid;
        float iv = sigf(gv[tid]);
        float fv = sigf(gv[32 + tid]);
        float gg = tanhf(gv[64 + tid]);
        float ov = sigf(gv[96 + tid]);
        float c = g_cdec[b][u];
        c = fv * c + iv * gg;
        float h = ov * tanhf(c);
        g_cdec[b][u] = c;
        g_hdec[slot ^ 1][b][u] = h;
        g_decs[t][b][u] = h;
    }
}

// ---------------- classifier input pack ----------------
__global__ void k_pack() {
    int m = blockIdx.x;            // m = b*T + t
    int b = m / Tq, t = m % Tq;
    int tid = threadIdx.x;         // 128
    float4* dst = (float4*)(g_clsin + (size_t)m * 2048);
    dst[tid]       = ((const float4*)&g_temb[b][t][0])[tid];
    dst[128 + tid] = ((const float4*)&g_ctxs[t][b][0])[tid];
    dst[256 + tid] = ((const float4*)&g_ctxs[t][b][0])[128 + tid];
    dst[384 + tid] = ((const float4*)&g_decs[t][b][0])[tid];
}

// ---------------- host ----------------
extern "C" void kernel_launch(void* const* d_in, const int* in_sizes, int n_in,
                              void* d_out, int out_size) {
    (void)in_sizes; (void)n_in; (void)out_size;
    const int*   src       = (const int*)d_in[0];
    const int*   tgt       = (const int*)d_in[1];
    const float* src_emb   = (const float*)d_in[2];
    const float* tgt_emb   = (const float*)d_in[3];
    const float* eWih_f    = (const float*)d_in[4];
    const float* eWhh_f    = (const float*)d_in[5];
    const float* ebih_f    = (const float*)d_in[6];
    const float* ebhh_f    = (const float*)d_in[7];
    const float* eWih_b    = (const float*)d_in[8];
    const float* eWhh_b    = (const float*)d_in[9];
    const float* ebih_b    = (const float*)d_in[10];
    const float* ebhh_b    = (const float*)d_in[11];
    const float* dWih      = (const float*)d_in[12];
    const float* dWhh      = (const float*)d_in[13];
    const float* dbih      = (const float*)d_in[14];
    const float* dbhh      = (const float*)d_in[15];
    const float* att1_W    = (const float*)d_in[16];
    const float* att1_b    = (const float*)d_in[17];
    const float* att2_W    = (const float*)d_in[18];
    const float* cls1_W    = (const float*)d_in[20];
    const float* cls1_b    = (const float*)d_in[21];
    const float* cls2_W    = (const float*)d_in[22];
    const float* cls2_b    = (const float*)d_in[23];
    float* out = (float*)d_out;

    float *p_xsrc, *p_Xf, *p_Xb, *p_encout, *p_P, *p_temb_tb, *p_Xdec, *p_clsin, *p_hid;
    cudaGetSymbolAddress((void**)&p_xsrc, g_xsrc);
    cudaGetSymbolAddress((void**)&p_Xf, g_Xf);
    cudaGetSymbolAddress((void**)&p_Xb, g_Xb);
    cudaGetSymbolAddress((void**)&p_encout, g_encout);
    cudaGetSymbolAddress((void**)&p_P, g_P);
    cudaGetSymbolAddress((void**)&p_temb_tb, g_temb_tb);
    cudaGetSymbolAddress((void**)&p_Xdec, g_Xdec);
    cudaGetSymbolAddress((void**)&p_clsin, g_clsin);
    cudaGetSymbolAddress((void**)&p_hid, g_hid);

    k_zero_state<<<256, 256>>>();
    k_gather_src<<<Sq * Bq, 128>>>(src, src_emb);
    k_gather_tgt<<<Bq * Tq, 128>>>(tgt, tgt_emb);

    // encoder input gate precompute: [3200,512] x [2048,512]^T
    k_mma<<<dim3(25, 16), 256>>>(p_xsrc, Eq, eWih_f, Eq, ebih_f, ebhh_f,
                                 p_Xf, G4, Sq * Bq, G4, Eq, 0);
    k_mma<<<dim3(25, 16), 256>>>(p_xsrc, Eq, eWih_b, Eq, ebih_b, ebhh_b,
                                 p_Xb, G4, Sq * Bq, G4, Eq, 0);

    for (int s = 0; s < Sq; s++)
        k_enc_step<<<dim3(16, 32, 2), 128>>>(s, eWhh_f, eWhh_b);

    // attention layer-1 enc part, hoisted: [3200,1024] x [1536 rows, first 1024 cols]^T
    k_mma<<<dim3(25, 12), 256>>>(p_encout, H2, att1_W, H3, att1_b, (const float*)nullptr,
                                 p_P, H3, Bq * Sq, H3, H2, 0);

    // decoder input gate precompute (embedding part)
    k_mma<<<dim3(25, 16), 256>>>(p_temb_tb, Eq, dWih, H3, dbih, dbhh,
                                 p_Xdec, G4, Tq * Bq, G4, Eq, 0);

    k_dec_init<<<64, 256>>>();

    for (int t = 0; t < Tq; t++) {
        k_qproj<<<dim3(12, 16), 256>>>(t, att1_W);
        k_attn<<<32, 512>>>(t, att2_W);
        k_dec_lstm<<<dim3(16, 32), 128>>>(t, dWih, dWhh);
    }

    k_pack<<<Bq * Tq, 128>>>();

    // classifier
    k_mma<<<dim3(25, 8), 256>>>(p_clsin, 2048, cls1_W, 2048, cls1_b, (const float*)nullptr,
                                p_hid, H2, Bq * Tq, H2, 2048, 1);
    k_mma<<<dim3(25, 250), 256>>>(p_hid, H2, cls2_W, H2, cls2_b, (const float*)nullptr,
                                  out, VTq, Bq * Tq, VTq, H2, 0);
}

// round 13
// speedup vs baseline: 2.3238x; 2.3238x over previous
#include <cuda_runtime.h>
#include <cstdint>
#include <cstddef>

#define Bq 32
#define Sq 100
#define Tq 100
#define Eq 512
#define Hq 512
#define G4 2048   // 4H
#define H2 1024   // 2H
#define H3 1536   // 3H
#define VTq 32000
#define NB 148    // persistent grid size (<= SM count, co-resident guaranteed)

// ---------------- scratch (static device globals; no allocation) ----------------
__device__ float g_xsrc[Sq * Bq * Eq];
__device__ float g_Xf[Sq * Bq * G4];
__device__ float g_Xb[Sq * Bq * G4];
__device__ float g_h[2][2][Bq][Hq];               // [slot][dir][b][u] encoder h ping-pong
__device__ float g_encout[Bq][Sq][H2];
__device__ float g_encT[Bq][H2][Sq];
__device__ float g_P[(size_t)Bq * Sq * H3];
__device__ float g_temb[Bq][Tq][Eq];
__device__ float g_temb_tb[Tq * Bq * Eq];
__device__ float g_Xdec[Tq * Bq * G4];
__device__ float g_hd[2][Bq][Hq];                 // decoder h ping-pong
__device__ float g_cd[Bq][Hq];                    // decoder initial c
__device__ float g_Qp[2][Bq][H3];                 // Q projection k-split partials
__device__ float g_sc[Bq][128];                   // attention scores
__device__ float g_gpart[2][G4][Bq];              // lstm gate partials (k-split)
__device__ float g_ctxs[Tq][Bq][H2];
__device__ float g_decs[Tq][Bq][Hq];
__device__ float g_clsin[(size_t)Bq * Tq * 2048];
__device__ float g_hid[(size_t)Bq * Tq * H2];

__device__ unsigned g_cnt = 0;
__device__ volatile unsigned g_gen = 0;

__device__ __forceinline__ float sigf(float x) { return 1.f / (1.f + __expf(-x)); }

__device__ __forceinline__ uint32_t f2tf(float x) {
    uint32_t r;
    asm("cvt.rna.tf32.f32 %0, %1;" : "=r"(r) : "f"(x));
    return r;
}

// software grid barrier: all NB blocks must participate
__device__ __forceinline__ void gridbar() {
    __syncthreads();
    __threadfence();                       // release my writes (also CCTL.IVALL)
    if (threadIdx.x == 0) {
        unsigned g = g_gen;
        if (atomicAdd(&g_cnt, 1u) == NB - 1) {
            atomicExch(&g_cnt, 0u);
            __threadfence();
            g_gen = g + 1;
        } else {
            while (g_gen == g) { }
        }
    }
    __syncthreads();
    __threadfence();                       // acquire: invalidate L1 before reads
}

// 32x32 tile micro-kernel: 2x2 per thread, float4 shared loads
__device__ __forceinline__ void mm32(const float (&Ws)[32][36], const float (&Xs)[32][36],
                                     int rx, int bx,
                                     float& a00, float& a01, float& a10, float& a11) {
#pragma unroll
    for (int kk = 0; kk < 32; kk += 4) {
        float4 w0 = *(const float4*)&Ws[rx][kk];
        float4 w1 = *(const float4*)&Ws[rx + 16][kk];
        float4 x0 = *(const float4*)&Xs[bx][kk];
        float4 x1 = *(const float4*)&Xs[bx + 16][kk];
        a00 += w0.x * x0.x + w0.y * x0.y + w0.z * x0.z + w0.w * x0.w;
        a01 += w0.x * x1.x + w0.y * x1.y + w0.z * x1.z + w0.w * x1.w;
        a10 += w1.x * x0.x + w1.y * x0.y + w1.z * x0.z + w1.w * x0.w;
        a11 += w1.x * x1.x + w1.y * x1.y + w1.z * x1.z + w1.w * x1.w;
    }
}

// ---------------- gathers ----------------
__global__ void k_gather_src(const int* __restrict__ src, const float* __restrict__ emb) {
    int m = blockIdx.x;            // m = s*B + b
    int s = m / Bq, b = m % Bq;
    int idx = src[b * Sq + s];
    float4 v = ((const float4*)(emb + (size_t)idx * Eq))[threadIdx.x];
    ((float4*)(g_xsrc + (size_t)m * Eq))[threadIdx.x] = v;
}

__global__ void k_gather_tgt(const int* __restrict__ tgt, const float* __restrict__ emb) {
    int m = blockIdx.x;            // m = b*T + t
    int b = m / Tq, t = m % Tq;
    int idx = tgt[m];
    float4 v = ((const float4*)(emb + (size_t)idx * Eq))[threadIdx.x];
    ((float4*)(&g_temb[b][t][0]))[threadIdx.x] = v;
    ((float4*)(g_temb_tb + ((size_t)t * Bq + b) * Eq))[threadIdx.x] = v;
}

// ---------------- tf32 tensor-core GEMM (unchanged) ----------------
#define SSTR 20
__global__ void __launch_bounds__(256) k_mma(
    const float* __restrict__ A, int lda,
    const float* __restrict__ W, int ldw,
    const float* __restrict__ bias1, const float* __restrict__ bias2,
    float* __restrict__ C, int ldc,
    int M, int N, int K, int do_relu)
{
    __shared__ uint32_t As[128 * SSTR];
    __shared__ uint32_t Ws[128 * SSTR];
    int tid = threadIdx.x;
    int bm = blockIdx.x * 128, bn = blockIdx.y * 128;

    int warp = tid >> 5, lane = tid & 31;
    int wm = warp & 1, wn = warp >> 1;
    int grp = lane >> 2, qid = lane & 3;

    float acc[4][4][4];
#pragma unroll
    for (int i = 0; i < 4; i++)
#pragma unroll
        for (int j = 0; j < 4; j++)
#pragma unroll
            for (int r = 0; r < 4; r++) acc[i][j][r] = 0.f;

    for (int k0 = 0; k0 < K; k0 += 16) {
#pragma unroll
        for (int i = 0; i < 2; i++) {
            int idx = tid * 2 + i;
            int row = idx >> 2, q = idx & 3;
            float4 av = *(const float4*)(A + (size_t)(bm + row) * lda + k0 + q * 4);
            float4 wv = *(const float4*)(W + (size_t)(bn + row) * ldw + k0 + q * 4);
            uint4 at = make_uint4(f2tf(av.x), f2tf(av.y), f2tf(av.z), f2tf(av.w));
            uint4 wt = make_uint4(f2tf(wv.x), f2tf(wv.y), f2tf(wv.z), f2tf(wv.w));
            *(uint4*)&As[row * SSTR + q * 4] = at;
            *(uint4*)&Ws[row * SSTR + q * 4] = wt;
        }
        __syncthreads();
#pragma unroll
        for (int kf = 0; kf < 2; kf++) {
            int kb = kf * 8;
            uint32_t a[4][4], b[4][2];
#pragma unroll
            for (int mf = 0; mf < 4; mf++) {
                int rb = (wm * 64 + mf * 16) * SSTR + kb;
                a[mf][0] = As[rb + grp * SSTR + qid];
                a[mf][1] = As[rb + (grp + 8) * SSTR + qid];
                a[mf][2] = As[rb + grp * SSTR + qid + 4];
                a[mf][3] = As[rb + (grp + 8) * SSTR + qid + 4];
            }
#pragma unroll
            for (int nf = 0; nf < 4; nf++) {
                int cb = (wn * 32 + nf * 8 + grp) * SSTR + kb;
                b[nf][0] = Ws[cb + qid];
                b[nf][1] = Ws[cb + qid + 4];
            }
#pragma unroll
            for (int mf = 0; mf < 4; mf++)
#pragma unroll
                for (int nf = 0; nf < 4; nf++) {
                    asm volatile(
                        "mma.sync.aligned.m16n8k8.row.col.f32.tf32.tf32.f32 "
                        "{%0,%1,%2,%3}, {%4,%5,%6,%7}, {%8,%9}, {%0,%1,%2,%3};\n"
                        : "+f"(acc[mf][nf][0]), "+f"(acc[mf][nf][1]),
                          "+f"(acc[mf][nf][2]), "+f"(acc[mf][nf][3])
                        : "r"(a[mf][0]), "r"(a[mf][1]), "r"(a[mf][2]), "r"(a[mf][3]),
                          "r"(b[nf][0]), "r"(b[nf][1]));
                }
        }
        __syncthreads();
    }

#pragma unroll
    for (int nf = 0; nf < 4; nf++) {
        int col = bn + wn * 32 + nf * 8 + qid * 2;
        float b0 = bias1[col], b1 = bias1[col + 1];
        if (bias2) { b0 += bias2[col]; b1 += bias2[col + 1]; }
#pragma unroll
        for (int mf = 0; mf < 4; mf++) {
            int row = bm + wm * 64 + mf * 16 + grp;
            float v0 = acc[mf][nf][0] + b0, v1 = acc[mf][nf][1] + b1;
            float v2 = acc[mf][nf][2] + b0, v3 = acc[mf][nf][3] + b1;
            if (do_relu) {
                v0 = fmaxf(v0, 0.f); v1 = fmaxf(v1, 0.f);
                v2 = fmaxf(v2, 0.f); v3 = fmaxf(v3, 0.f);
            }
            *(float2*)&C[(size_t)row * ldc + col] = make_float2(v0, v1);
            *(float2*)&C[(size_t)(row + 8) * ldc + col] = make_float2(v2, v3);
        }
    }
}

// ---------------- persistent encoder loop ----------------
// 128 working blocks: bid -> (dir = bid>>6, units u0 = (bid&63)*8, rows = 4 gates x 8 units)
__global__ void __launch_bounds__(256) k_enc_loop(const float* __restrict__ Whh_f,
                                                  const float* __restrict__ Whh_b) {
    __shared__ float Ws[32][36];
    __shared__ float Hs[32][36];
    __shared__ float sacc[32][33];
    __shared__ float c_s[8][32];
    int tid = threadIdx.x, bid = blockIdx.x;

    // zero initial h (slot 0) and local c
    for (int i = bid * 256 + tid; i < 2 * Bq * Hq; i += NB * 256)
        ((float*)g_h[0])[i] = 0.f;
    c_s[tid >> 5][tid & 31] = 0.f;
    gridbar();

    bool active = bid < 128;
    int d = bid >> 6;
    int u0 = (bid & 63) * 8;
    const float* W = d ? Whh_b : Whh_f;
    const float* X = d ? g_Xb : g_Xf;
    int rx = tid >> 4, bx = tid & 15;
    int l_r = tid >> 3, l_kq = (tid & 7) * 4;
    int l_grow = ((l_r >> 3) << 9) + u0 + (l_r & 7);

    for (int s = 0; s < Sq; s++) {
        int slot = s & 1;
        if (active) {
            float a00 = 0, a01 = 0, a10 = 0, a11 = 0;
            for (int k0 = 0; k0 < Hq; k0 += 32) {
                float4 wv = *(const float4*)(W + (size_t)l_grow * Hq + k0 + l_kq);
                float4 hv = __ldcg((const float4*)&g_h[slot][d][l_r][k0 + l_kq]);
                *(float4*)&Ws[l_r][l_kq] = wv;
                *(float4*)&Hs[l_r][l_kq] = hv;
                __syncthreads();
                mm32(Ws, Hs, rx, bx, a00, a01, a10, a11);
                __syncthreads();
            }
            sacc[rx][bx] = a00;      sacc[rx][bx + 16] = a01;
            sacc[rx + 16][bx] = a10; sacc[rx + 16][bx + 16] = a11;
            __syncthreads();
            int uj = tid >> 5, b = tid & 31;
            int seff = d ? (Sq - 1 - s) : s;
            const float* Xp = X + ((size_t)seff * Bq + b) * G4;
            int u = u0 + uj;
            float gi = sacc[uj][b]      + Xp[u];
            float gf = sacc[8 + uj][b]  + Xp[512 + u];
            float gg = sacc[16 + uj][b] + Xp[1024 + u];
            float go = sacc[24 + uj][b] + Xp[1536 + u];
            float c = c_s[uj][b];
            c = sigf(gf) * c + sigf(gi) * tanhf(gg);
            float h = sigf(go) * tanhf(c);
            c_s[uj][b] = c;
            g_h[slot ^ 1][d][b][u] = h;
            g_encout[b][seff][(d << 9) + u] = h;
            g_encT[b][(d << 9) + u][seff] = h;
            if (d == 0 && s == Sq - 1) {
                g_hd[0][b][u] = h;       // decoder init h
                g_cd[b][u] = c;          // decoder init c
            }
        }
        gridbar();
    }
}

// ---------------- persistent decoder loop ----------------
// per step: A qproj(k-split 96 blks) | B scores(800 warp-tasks) | C softmax+ctx(128 blks)
//           D gates GEMM(k-split 128 blks) | E combine+LSTM(64 blks)
__global__ void __launch_bounds__(256) k_dec_loop(
    const float* __restrict__ att1_W, const float* __restrict__ att2_W,
    const float* __restrict__ dWih, const float* __restrict__ dWhh)
{
    __shared__ float Ws[32][36];
    __shared__ float Xs[32][36];
    __shared__ float sacc[32][33];
    __shared__ float a2s[H3];
    __shared__ float sw[128];
    __shared__ float c_s[8][32];
    int tid = threadIdx.x, bid = blockIdx.x;
    int rx = tid >> 4, bx = tid & 15;
    int l_r = tid >> 3, l_kq = (tid & 7) * 4;

    for (int j = tid; j < H3; j += 256) a2s[j] = att2_W[j];
    if (bid < 64) {
        int uj = tid >> 5, b = tid & 31;
        c_s[uj][b] = __ldcg(&g_cd[b][(bid << 3) + uj]);
    }
    gridbar();

    for (int t = 0; t < Tq; t++) {
        int slot = t & 1;
        // ---- phase A: Q partials = h @ att1_W[:,1024:]^T ----
        if (bid < 96) {
            int kh = bid >= 48;
            int j0 = (bid % 48) * 32;
            float a00 = 0, a01 = 0, a10 = 0, a11 = 0;
            for (int kc = 0; kc < 8; kc++) {
                int k0 = kh * 256 + kc * 32;
                *(float4*)&Ws[l_r][l_kq] =
                    *(const float4*)(att1_W + (size_t)(j0 + l_r) * H3 + H2 + k0 + l_kq);
                *(float4*)&Xs[l_r][l_kq] = __ldcg((const float4*)&g_hd[slot][l_r][k0 + l_kq]);
                __syncthreads();
                mm32(Ws, Xs, rx, bx, a00, a01, a10, a11);
                __syncthreads();
            }
            sacc[rx][bx] = a00;      sacc[rx][bx + 16] = a01;
            sacc[rx + 16][bx] = a10; sacc[rx + 16][bx + 16] = a11;
            __syncthreads();
#pragma unroll
            for (int i = 0; i < 4; i++) {
                int cell = i * 256 + tid;
                int r = cell >> 5, b = cell & 31;
                g_Qp[kh][b][j0 + r] = sacc[r][b];
            }
        }
        gridbar();
        // ---- phase B: scores sc[b][s] = relu(P+Q).a2 ----
        {
            int wg = bid * 8 + (tid >> 5);
            if (wg < 800) {
                int b = wg / 25, q = wg % 25;
                int lane = tid & 31;
                float ac0 = 0, ac1 = 0, ac2 = 0, ac3 = 0;
                const float* Pb = g_P + ((size_t)b * Sq + q * 4) * H3;
                for (int j = lane; j < H3; j += 32) {
                    float qv = __ldcg(&g_Qp[0][b][j]) + __ldcg(&g_Qp[1][b][j]);
                    float av = a2s[j];
                    ac0 += fmaxf(Pb[j] + qv, 0.f) * av;
                    ac1 += fmaxf(Pb[H3 + j] + qv, 0.f) * av;
                    ac2 += fmaxf(Pb[2 * H3 + j] + qv, 0.f) * av;
                    ac3 += fmaxf(Pb[3 * H3 + j] + qv, 0.f) * av;
                }
#pragma unroll
                for (int o = 16; o; o >>= 1) {
                    ac0 += __shfl_xor_sync(0xffffffffu, ac0, o);
                    ac1 += __shfl_xor_sync(0xffffffffu, ac1, o);
                    ac2 += __shfl_xor_sync(0xffffffffu, ac2, o);
                    ac3 += __shfl_xor_sync(0xffffffffu, ac3, o);
                }
                if (lane == 0) {
                    g_sc[b][q * 4 + 0] = ac0;
                    g_sc[b][q * 4 + 1] = ac1;
                    g_sc[b][q * 4 + 2] = ac2;
                    g_sc[b][q * 4 + 3] = ac3;
                }
            }
        }
        gridbar();
        // ---- phase C: softmax + ctx ----
        if (bid < 128) {
            int b = bid >> 2, kc = bid & 3;
            if (tid < 100) sw[tid] = __ldcg(&g_sc[b][tid]);
            __syncthreads();
            float mx = -1e30f;
#pragma unroll 4
            for (int i = 0; i < 100; i++) mx = fmaxf(mx, sw[i]);
            float ev = (tid < 100) ? __expf(sw[tid] - mx) : 0.f;
            __syncthreads();
            if (tid < 100) sw[tid] = ev;
            __syncthreads();
            float sum = 0.f;
#pragma unroll 4
            for (int i = 0; i < 100; i++) sum += sw[i];
            float inv = 1.f / sum;
            int k = kc * 256 + tid;
            const float* eT = &g_encT[b][k][0];
            float acc = 0.f;
#pragma unroll
            for (int s4 = 0; s4 < 100; s4 += 4) {
                float4 e4 = *(const float4*)(eT + s4);
                acc += sw[s4] * e4.x + sw[s4 + 1] * e4.y + sw[s4 + 2] * e4.z + sw[s4 + 3] * e4.w;
            }
            g_ctxs[t][b][k] = acc * inv;
        }
        gridbar();
        // ---- phase D: gate GEMM partials over K=1536 (ctx 1024 | h 512), k-split 2 ----
        if (bid < 128) {
            int kh = bid >> 6;
            int u0 = (bid & 63) * 8;
            int grow = ((l_r >> 3) << 9) + u0 + (l_r & 7);
            float a00 = 0, a01 = 0, a10 = 0, a11 = 0;
            for (int kc = 0; kc < 24; kc++) {
                int k0 = kh * 768 + kc * 32;
                const float* Wp;
                const float* xp;
                if (k0 < 1024) {
                    Wp = dWih + (size_t)grow * H3 + 512 + k0;
                    xp = &g_ctxs[t][l_r][k0];
                } else {
                    Wp = dWhh + (size_t)grow * Hq + (k0 - 1024);
                    xp = &g_hd[slot][l_r][k0 - 1024];
                }
                *(float4*)&Ws[l_r][l_kq] = *(const float4*)(Wp + l_kq);
                *(float4*)&Xs[l_r][l_kq] = __ldcg((const float4*)(xp + l_kq));
                __syncthreads();
                mm32(Ws, Xs, rx, bx, a00, a01, a10, a11);
                __syncthreads();
            }
            sacc[rx][bx] = a00;      sacc[rx][bx + 16] = a01;
            sacc[rx + 16][bx] = a10; sacc[rx + 16][bx + 16] = a11;
            __syncthreads();
#pragma unroll
            for (int i = 0; i < 4; i++) {
                int cell = i * 256 + tid;
                int r = cell >> 5, b = cell & 31;
                int gr = ((r >> 3) << 9) + u0 + (r & 7);
                g_gpart[kh][gr][b] = sacc[r][b];
            }
        }
        gridbar();
        // ---- phase E: combine partials + LSTM update ----
        if (bid < 64) {
            int uj = tid >> 5, b = tid & 31;
            int u = (bid << 3) + uj;
            const float* Xp = g_Xdec + ((size_t)t * Bq + b) * G4;
            float gi = __ldcg(&g_gpart[0][u][b])        + __ldcg(&g_gpart[1][u][b])        + Xp[u];
            float gf = __ldcg(&g_gpart[0][512 + u][b])  + __ldcg(&g_gpart[1][512 + u][b])  + Xp[512 + u];
            float gg = __ldcg(&g_gpart[0][1024 + u][b]) + __ldcg(&g_gpart[1][1024 + u][b]) + Xp[1024 + u];
            float go = __ldcg(&g_gpart[0][1536 + u][b]) + __ldcg(&g_gpart[1][1536 + u][b]) + Xp[1536 + u];
            float c = c_s[uj][b];
            c = sigf(gf) * c + sigf(gi) * tanhf(gg);
            float h = sigf(go) * tanhf(c);
            c_s[uj][b] = c;
            g_hd[slot ^ 1][b][u] = h;
            g_decs[t][b][u] = h;
        }
        gridbar();
    }
}

// ---------------- classifier input pack ----------------
__global__ void k_pack() {
    int m = blockIdx.x;            // m = b*T + t
    int b = m / Tq, t = m % Tq;
    int tid = threadIdx.x;         // 128
    float4* dst = (float4*)(g_clsin + (size_t)m * 2048);
    dst[tid]       = ((const float4*)&g_temb[b][t][0])[tid];
    dst[128 + tid] = ((const float4*)&g_ctxs[t][b][0])[tid];
    dst[256 + tid] = ((const float4*)&g_ctxs[t][b][0])[128 + tid];
    dst[384 + tid] = ((const float4*)&g_decs[t][b][0])[tid];
}

// ---------------- host ----------------
extern "C" void kernel_launch(void* const* d_in, const int* in_sizes, int n_in,
                              void* d_out, int out_size) {
    (void)in_sizes; (void)n_in; (void)out_size;
    const int*   src       = (const int*)d_in[0];
    const int*   tgt       = (const int*)d_in[1];
    const float* src_emb   = (const float*)d_in[2];
    const float* tgt_emb   = (const float*)d_in[3];
    const float* eWih_f    = (const float*)d_in[4];
    const float* eWhh_f    = (const float*)d_in[5];
    const float* ebih_f    = (const float*)d_in[6];
    const float* ebhh_f    = (const float*)d_in[7];
    const float* eWih_b    = (const float*)d_in[8];
    const float* eWhh_b    = (const float*)d_in[9];
    const float* ebih_b    = (const float*)d_in[10];
    const float* ebhh_b    = (const float*)d_in[11];
    const float* dWih      = (const float*)d_in[12];
    const float* dWhh      = (const float*)d_in[13];
    const float* dbih      = (const float*)d_in[14];
    const float* dbhh      = (const float*)d_in[15];
    const float* att1_W    = (const float*)d_in[16];
    const float* att1_b    = (const float*)d_in[17];
    const float* att2_W    = (const float*)d_in[18];
    const float* cls1_W    = (const float*)d_in[20];
    const float* cls1_b    = (const float*)d_in[21];
    const float* cls2_W    = (const float*)d_in[22];
    const float* cls2_b    = (const float*)d_in[23];
    float* out = (float*)d_out;

    float *p_xsrc, *p_Xf, *p_Xb, *p_encout, *p_P, *p_temb_tb, *p_Xdec, *p_clsin, *p_hid;
    cudaGetSymbolAddress((void**)&p_xsrc, g_xsrc);
    cudaGetSymbolAddress((void**)&p_Xf, g_Xf);
    cudaGetSymbolAddress((void**)&p_Xb, g_Xb);
    cudaGetSymbolAddress((void**)&p_encout, g_encout);
    cudaGetSymbolAddress((void**)&p_P, g_P);
    cudaGetSymbolAddress((void**)&p_temb_tb, g_temb_tb);
    cudaGetSymbolAddress((void**)&p_Xdec, g_Xdec);
    cudaGetSymbolAddress((void**)&p_clsin, g_clsin);
    cudaGetSymbolAddress((void**)&p_hid, g_hid);

    k_gather_src<<<Sq * Bq, 128>>>(src, src_emb);
    k_gather_tgt<<<Bq * Tq, 128>>>(tgt, tgt_emb);

    // encoder input gates
    k_mma<<<dim3(25, 16), 256>>>(p_xsrc, Eq, eWih_f, Eq, ebih_f, ebhh_f,
                                 p_Xf, G4, Sq * Bq, G4, Eq, 0);
    k_mma<<<dim3(25, 16), 256>>>(p_xsrc, Eq, eWih_b, Eq, ebih_b, ebhh_b,
                                 p_Xb, G4, Sq * Bq, G4, Eq, 0);

    // persistent encoder (100 steps, 1 launch)
    k_enc_loop<<<NB, 256>>>(eWhh_f, eWhh_b);

    // attention layer-1 enc part (hoisted)
    k_mma<<<dim3(25, 12), 256>>>(p_encout, H2, att1_W, H3, att1_b, (const float*)nullptr,
                                 p_P, H3, Bq * Sq, H3, H2, 0);

    // decoder input gates (embedding part)
    k_mma<<<dim3(25, 16), 256>>>(p_temb_tb, Eq, dWih, H3, dbih, dbhh,
                                 p_Xdec, G4, Tq * Bq, G4, Eq, 0);

    // persistent decoder (100 steps, 1 launch)
    k_dec_loop<<<NB, 256>>>(att1_W, att2_W, dWih, dWhh);

    k_pack<<<Bq * Tq, 128>>>();

    // classifier
    k_mma<<<dim3(25, 8), 256>>>(p_clsin, 2048, cls1_W, 2048, cls1_b, (const float*)nullptr,
                                p_hid, H2, Bq * Tq, H2, 2048, 1);
    k_mma<<<dim3(25, 250), 256>>>(p_hid, H2, cls2_W, H2, cls2_b, (const float*)nullptr,
                                  out, VTq, Bq * Tq, VTq, H2, 0);
}

// round 14
// speedup vs baseline: 2.7584x; 1.1871x over previous
#include <cuda_runtime.h>
#include <cstdint>
#include <cstddef>

#define Bq 32
#define Sq 100
#define Tq 100
#define Eq 512
#define Hq 512
#define G4 2048   // 4H
#define H2 1024   // 2H
#define H3 1536   // 3H
#define VTq 32000
#define NB 148    // persistent grid size (<= SM count, co-resident guaranteed)

// ---------------- scratch (static device globals; no allocation) ----------------
__device__ float g_xsrc[Sq * Bq * Eq];
__device__ float g_Xf[Sq * Bq * G4];
__device__ float g_Xb[Sq * Bq * G4];
__device__ float g_h[2][2][Bq][Hq];               // [slot][dir][b][u] encoder h ping-pong
__device__ float g_encout[Bq][Sq][H2];
__device__ float g_encT[Bq][H2][Sq];
__device__ float g_P[(size_t)Bq * Sq * H3];
__device__ float g_temb[Bq][Tq][Eq];
__device__ float g_temb_tb[Tq * Bq * Eq];
__device__ float g_Xdec[Tq * Bq * G4];
__device__ float g_hd[2][Bq][Hq];                 // decoder h ping-pong
__device__ float g_cd[Bq][Hq];                    // decoder initial c
__device__ float g_Qp[2][Bq][H3];                 // Q projection k-split partials
__device__ float g_gpart[2][G4][Bq];              // lstm gate partials (k-split)
__device__ float g_ctxs[Tq][Bq][H2];
__device__ float g_decs[Tq][Bq][Hq];
__device__ float g_clsin[(size_t)Bq * Tq * 2048];
__device__ float g_hid[(size_t)Bq * Tq * H2];

__device__ unsigned g_cnt = 0;
__device__ volatile unsigned g_gen = 0;

__device__ __forceinline__ float sigf(float x) { return 1.f / (1.f + __expf(-x)); }

__device__ __forceinline__ uint32_t f2tf(float x) {
    uint32_t r;
    asm("cvt.rna.tf32.f32 %0, %1;" : "=r"(r) : "f"(x));
    return r;
}

__device__ __forceinline__ void cpa16(void* dst, const void* src) {
    uint32_t d = (uint32_t)__cvta_generic_to_shared(dst);
    asm volatile("cp.async.ca.shared.global [%0], [%1], 16;\n" :: "r"(d), "l"(src));
}
#define CPA_COMMIT() asm volatile("cp.async.commit_group;\n" ::: "memory")
#define CPA_WAIT0()  asm volatile("cp.async.wait_group 0;\n" ::: "memory")

// software grid barrier: all NB blocks must participate
__device__ __forceinline__ void gridbar() {
    __syncthreads();
    __threadfence();                       // release my writes
    if (threadIdx.x == 0) {
        unsigned g = g_gen;
        if (atomicAdd(&g_cnt, 1u) == NB - 1) {
            atomicExch(&g_cnt, 0u);
            __threadfence();
            g_gen = g + 1;
        } else {
            while (g_gen == g) { }
        }
    }
    __syncthreads();
    __threadfence();                       // acquire
}

// ---------------- gathers ----------------
__global__ void k_gather_src(const int* __restrict__ src, const float* __restrict__ emb) {
    int m = blockIdx.x;            // m = s*B + b
    int s = m / Bq, b = m % Bq;
    int idx = src[b * Sq + s];
    float4 v = ((const float4*)(emb + (size_t)idx * Eq))[threadIdx.x];
    ((float4*)(g_xsrc + (size_t)m * Eq))[threadIdx.x] = v;
}

__global__ void k_gather_tgt(const int* __restrict__ tgt, const float* __restrict__ emb) {
    int m = blockIdx.x;            // m = b*T + t
    int b = m / Tq, t = m % Tq;
    int idx = tgt[m];
    float4 v = ((const float4*)(emb + (size_t)idx * Eq))[threadIdx.x];
    ((float4*)(&g_temb[b][t][0]))[threadIdx.x] = v;
    ((float4*)(g_temb_tb + ((size_t)t * Bq + b) * Eq))[threadIdx.x] = v;
}

// ---------------- tf32 tensor-core GEMM with cp.async double buffering ----------------
// C[M,N] = act(A[M,K] @ W[N,K]^T + bias1 (+bias2)); tiles 128x128, BK=16.
#define SSTR 20
__global__ void __launch_bounds__(256, 2) k_mma(
    const float* __restrict__ A, int lda,
    const float* __restrict__ W, int ldw,
    const float* __restrict__ bias1, const float* __restrict__ bias2,
    float* __restrict__ C, int ldc,
    int M, int N, int K, int do_relu)
{
    __shared__ float Asf[2][128 * SSTR];
    __shared__ float Wsf[2][128 * SSTR];
    int tid = threadIdx.x;
    int bm = blockIdx.x * 128, bn = blockIdx.y * 128;

    int warp = tid >> 5, lane = tid & 31;
    int wm = warp & 1, wn = warp >> 1;
    int grp = lane >> 2, qid = lane & 3;

    int l_row0 = (tid * 2) >> 2, l_q0 = (tid * 2) & 3;
    int l_row1 = (tid * 2 + 1) >> 2, l_q1 = (tid * 2 + 1) & 3;

    float acc[4][4][4];
#pragma unroll
    for (int i = 0; i < 4; i++)
#pragma unroll
        for (int j = 0; j < 4; j++)
#pragma unroll
            for (int r = 0; r < 4; r++) acc[i][j][r] = 0.f;

    // prologue: stage tile 0
    cpa16(&Asf[0][l_row0 * SSTR + l_q0 * 4], A + (size_t)(bm + l_row0) * lda + l_q0 * 4);
    cpa16(&Wsf[0][l_row0 * SSTR + l_q0 * 4], W + (size_t)(bn + l_row0) * ldw + l_q0 * 4);
    cpa16(&Asf[0][l_row1 * SSTR + l_q1 * 4], A + (size_t)(bm + l_row1) * lda + l_q1 * 4);
    cpa16(&Wsf[0][l_row1 * SSTR + l_q1 * 4], W + (size_t)(bn + l_row1) * ldw + l_q1 * 4);
    CPA_COMMIT();

    int nt = K >> 4;
    for (int kt = 0; kt < nt; kt++) {
        int cur = kt & 1;
        CPA_WAIT0();
        __syncthreads();
        if (kt + 1 < nt) {
            int k0 = (kt + 1) << 4;
            int nx = cur ^ 1;
            cpa16(&Asf[nx][l_row0 * SSTR + l_q0 * 4], A + (size_t)(bm + l_row0) * lda + k0 + l_q0 * 4);
            cpa16(&Wsf[nx][l_row0 * SSTR + l_q0 * 4], W + (size_t)(bn + l_row0) * ldw + k0 + l_q0 * 4);
            cpa16(&Asf[nx][l_row1 * SSTR + l_q1 * 4], A + (size_t)(bm + l_row1) * lda + k0 + l_q1 * 4);
            cpa16(&Wsf[nx][l_row1 * SSTR + l_q1 * 4], W + (size_t)(bn + l_row1) * ldw + k0 + l_q1 * 4);
            CPA_COMMIT();
        }
#pragma unroll
        for (int kf = 0; kf < 2; kf++) {
            int kb = kf * 8;
            uint32_t a[4][4], b[4][2];
#pragma unroll
            for (int mf = 0; mf < 4; mf++) {
                int rb = (wm * 64 + mf * 16) * SSTR + kb;
                a[mf][0] = f2tf(Asf[cur][rb + grp * SSTR + qid]);
                a[mf][1] = f2tf(Asf[cur][rb + (grp + 8) * SSTR + qid]);
                a[mf][2] = f2tf(Asf[cur][rb + grp * SSTR + qid + 4]);
                a[mf][3] = f2tf(Asf[cur][rb + (grp + 8) * SSTR + qid + 4]);
            }
#pragma unroll
            for (int nf = 0; nf < 4; nf++) {
                int cb = (wn * 32 + nf * 8 + grp) * SSTR + kb;
                b[nf][0] = f2tf(Wsf[cur][cb + qid]);
                b[nf][1] = f2tf(Wsf[cur][cb + qid + 4]);
            }
#pragma unroll
            for (int mf = 0; mf < 4; mf++)
#pragma unroll
                for (int nf = 0; nf < 4; nf++) {
                    asm volatile(
                        "mma.sync.aligned.m16n8k8.row.col.f32.tf32.tf32.f32 "
                        "{%0,%1,%2,%3}, {%4,%5,%6,%7}, {%8,%9}, {%0,%1,%2,%3};\n"
                        : "+f"(acc[mf][nf][0]), "+f"(acc[mf][nf][1]),
                          "+f"(acc[mf][nf][2]), "+f"(acc[mf][nf][3])
                        : "r"(a[mf][0]), "r"(a[mf][1]), "r"(a[mf][2]), "r"(a[mf][3]),
                          "r"(b[nf][0]), "r"(b[nf][1]));
                }
        }
        __syncthreads();
    }

#pragma unroll
    for (int nf = 0; nf < 4; nf++) {
        int col = bn + wn * 32 + nf * 8 + qid * 2;
        float b0 = bias1[col], b1 = bias1[col + 1];
        if (bias2) { b0 += bias2[col]; b1 += bias2[col + 1]; }
#pragma unroll
        for (int mf = 0; mf < 4; mf++) {
            int row = bm + wm * 64 + mf * 16 + grp;
            float v0 = acc[mf][nf][0] + b0, v1 = acc[mf][nf][1] + b1;
            float v2 = acc[mf][nf][2] + b0, v3 = acc[mf][nf][3] + b1;
            if (do_relu) {
                v0 = fmaxf(v0, 0.f); v1 = fmaxf(v1, 0.f);
                v2 = fmaxf(v2, 0.f); v3 = fmaxf(v3, 0.f);
            }
            *(float2*)&C[(size_t)row * ldc + col] = make_float2(v0, v1);
            *(float2*)&C[(size_t)(row + 8) * ldc + col] = make_float2(v2, v3);
        }
    }
}

// ======== 4x4-tile 32x32xK block matmul helpers (persistent loops) ========
// Block = 256 threads = 4 k-groups x 64 threads (8 rx x 8 bx).
// Thread owns rows {rx,rx+8,rx+16,rx+24} x batches {bx,bx+8,bx+16,bx+24} (conflict-free LDS).
// Shared Ws/Xs[4][32][36] per 32-k chunk; partials to sacc overlay, combined by caller.
#define SAC(kg, r, b) sac[((kg) * 32 + (r)) * 33 + (b)]

__device__ __forceinline__ void mm4x4(const float (&Ws)[4][32][36], const float (&Xs)[4][32][36],
                                      int kg, int rx, int bx, float (&acc)[4][4]) {
#pragma unroll
    for (int kq = 0; kq < 8; kq++) {
        float4 w0 = *(const float4*)&Ws[kg][rx][kq * 4];
        float4 w1 = *(const float4*)&Ws[kg][rx + 8][kq * 4];
        float4 w2 = *(const float4*)&Ws[kg][rx + 16][kq * 4];
        float4 w3 = *(const float4*)&Ws[kg][rx + 24][kq * 4];
        float4 x0 = *(const float4*)&Xs[kg][bx][kq * 4];
        float4 x1 = *(const float4*)&Xs[kg][bx + 8][kq * 4];
        float4 x2 = *(const float4*)&Xs[kg][bx + 16][kq * 4];
        float4 x3 = *(const float4*)&Xs[kg][bx + 24][kq * 4];
        float4 wv[4] = {w0, w1, w2, w3};
        float4 xv[4] = {x0, x1, x2, x3};
#pragma unroll
        for (int i = 0; i < 4; i++)
#pragma unroll
            for (int j = 0; j < 4; j++)
                acc[i][j] += wv[i].x * xv[j].x + wv[i].y * xv[j].y
                           + wv[i].z * xv[j].z + wv[i].w * xv[j].w;
    }
}

// ---------------- persistent encoder loop ----------------
// 128 working blocks: bid -> (dir = bid>>6, units u0 = (bid&63)*8, rows = 4 gates x 8 units)
__global__ void __launch_bounds__(256) k_enc_loop(const float* __restrict__ Whh_f,
                                                  const float* __restrict__ Whh_b) {
    __shared__ float Ws[4][32][36];
    __shared__ float Xs[4][32][36];
    __shared__ float c_s[8][32];
    float* sac = &Ws[0][0][0];   // overlay: partial accumulators after compute
    int tid = threadIdx.x, bid = blockIdx.x;

    for (int i = bid * 256 + tid; i < 2 * Bq * Hq; i += NB * 256)
        ((float*)g_h[0])[i] = 0.f;
    c_s[tid >> 5][tid & 31] = 0.f;
    gridbar();

    bool active = bid < 128;
    int d = bid >> 6;
    int u0 = (bid & 63) * 8;
    const float* W = d ? Whh_b : Whh_f;
    const float* X = d ? g_Xb : g_Xf;
    int kg = tid >> 6, t64 = tid & 63, rx = t64 >> 3, bx = t64 & 7;

    for (int s = 0; s < Sq; s++) {
        int slot = s & 1;
        if (active) {
            float acc[4][4];
#pragma unroll
            for (int i = 0; i < 4; i++)
#pragma unroll
                for (int j = 0; j < 4; j++) acc[i][j] = 0.f;

            for (int c = 0; c < 4; c++) {
#pragma unroll
                for (int i = 0; i < 4; i++) {
                    int idx = tid * 4 + i;
                    int kgs = idx >> 8, r = (idx >> 3) & 31, q = idx & 7;
                    int k = kgs * 128 + c * 32 + q * 4;
                    int grow = ((r >> 3) << 9) + u0 + (r & 7);
                    *(float4*)&Ws[kgs][r][q * 4] = *(const float4*)(W + (size_t)grow * Hq + k);
                    *(float4*)&Xs[kgs][r][q * 4] = __ldcg((const float4*)&g_h[slot][d][r][k]);
                }
                __syncthreads();
                mm4x4(Ws, Xs, kg, rx, bx, acc);
                __syncthreads();
            }
            // write partials into overlay
#pragma unroll
            for (int i = 0; i < 4; i++)
#pragma unroll
                for (int j = 0; j < 4; j++)
                    SAC(kg, rx + 8 * i, bx + 8 * j) = acc[i][j];
            __syncthreads();
            // epilogue: combine k-groups + LSTM cell
            int uj = tid >> 5, b = tid & 31;
            int seff = d ? (Sq - 1 - s) : s;
            const float* Xp = X + ((size_t)seff * Bq + b) * G4;
            int u = u0 + uj;
            float gi = Xp[u], gf = Xp[512 + u], gg = Xp[1024 + u], go = Xp[1536 + u];
#pragma unroll
            for (int k2 = 0; k2 < 4; k2++) {
                gi += SAC(k2, uj, b);
                gf += SAC(k2, 8 + uj, b);
                gg += SAC(k2, 16 + uj, b);
                go += SAC(k2, 24 + uj, b);
            }
            float c = c_s[uj][b];
            c = sigf(gf) * c + sigf(gi) * tanhf(gg);
            float h = sigf(go) * tanhf(c);
            c_s[uj][b] = c;
            g_h[slot ^ 1][d][b][u] = h;
            g_encout[b][seff][(d << 9) + u] = h;
            g_encT[b][(d << 9) + u][seff] = h;
            if (d == 0 && s == Sq - 1) {
                g_hd[0][b][u] = h;
                g_cd[b][u] = c;
            }
        }
        gridbar();
    }
}

// ---------------- persistent decoder loop ----------------
// per step (4 barriers): A qproj(96 blks, ksplit 2) | BC scores+softmax+ctx(32 blks)
//                        D gates GEMM(128 blks, ksplit 2) | E combine+LSTM(64 blks)
__global__ void __launch_bounds__(256) k_dec_loop(
    const float* __restrict__ att1_W, const float* __restrict__ att2_W,
    const float* __restrict__ dWih, const float* __restrict__ dWhh)
{
    __shared__ float Ws[4][32][36];
    __shared__ float Xs[4][32][36];
    __shared__ float a2s[H3];
    __shared__ float sw[128];
    __shared__ float c_s[8][32];
    float* sac = &Ws[0][0][0];
    int tid = threadIdx.x, bid = blockIdx.x;
    int kg = tid >> 6, t64 = tid & 63, rx = t64 >> 3, bx = t64 & 7;

    for (int j = tid; j < H3; j += 256) a2s[j] = att2_W[j];
    if (bid < 64) {
        int uj = tid >> 5, b = tid & 31;
        c_s[uj][b] = __ldcg(&g_cd[b][(bid << 3) + uj]);
    }
    gridbar();

    for (int t = 0; t < Tq; t++) {
        int slot = t & 1;
        // ---- phase A: Qp[kh][b][j] partials = h @ att1_W[:,1024:]^T (k-split 2) ----
        if (bid < 96) {
            int kh = bid >= 48;
            int j0 = (bid % 48) * 32;
            float acc[4][4];
#pragma unroll
            for (int i = 0; i < 4; i++)
#pragma unroll
                for (int j = 0; j < 4; j++) acc[i][j] = 0.f;
            for (int c = 0; c < 2; c++) {
#pragma unroll
                for (int i = 0; i < 4; i++) {
                    int idx = tid * 4 + i;
                    int kgs = idx >> 8, r = (idx >> 3) & 31, q = idx & 7;
                    int k = kh * 256 + kgs * 64 + c * 32 + q * 4;
                    *(float4*)&Ws[kgs][r][q * 4] =
                        *(const float4*)(att1_W + (size_t)(j0 + r) * H3 + H2 + k);
                    *(float4*)&Xs[kgs][r][q * 4] = __ldcg((const float4*)&g_hd[slot][r][k]);
                }
                __syncthreads();
                mm4x4(Ws, Xs, kg, rx, bx, acc);
                __syncthreads();
            }
#pragma unroll
            for (int i = 0; i < 4; i++)
#pragma unroll
                for (int j = 0; j < 4; j++)
                    SAC(kg, rx + 8 * i, bx + 8 * j) = acc[i][j];
            __syncthreads();
#pragma unroll
            for (int i = 0; i < 4; i++) {
                int cell = i * 256 + tid;
                int r = cell >> 5, b = cell & 31;
                g_Qp[kh][b][j0 + r] = SAC(0, r, b) + SAC(1, r, b) + SAC(2, r, b) + SAC(3, r, b);
            }
        }
        gridbar();
        // ---- phase BC: scores + softmax + ctx, one block per batch ----
        if (bid < 32) {
            int b = bid;
            int warp = tid >> 5, lane = tid & 31;
            for (int s = warp; s < Sq; s += 8) {
                const float* Pp = g_P + ((size_t)b * Sq + s) * H3;
                float acc = 0.f;
#pragma unroll
                for (int jj = 0; jj < 12; jj++) {
                    int j = jj * 128 + lane * 4;
                    float4 p = *(const float4*)(Pp + j);
                    float4 q0 = __ldcg((const float4*)&g_Qp[0][b][j]);
                    float4 q1 = __ldcg((const float4*)&g_Qp[1][b][j]);
                    float4 a = *(const float4*)&a2s[j];
                    acc += fmaxf(p.x + q0.x + q1.x, 0.f) * a.x
                         + fmaxf(p.y + q0.y + q1.y, 0.f) * a.y
                         + fmaxf(p.z + q0.z + q1.z, 0.f) * a.z
                         + fmaxf(p.w + q0.w + q1.w, 0.f) * a.w;
                }
#pragma unroll
                for (int o = 16; o; o >>= 1) acc += __shfl_xor_sync(0xffffffffu, acc, o);
                if (!lane) sw[s] = acc;
            }
            __syncthreads();
            float mx = -1e30f;
#pragma unroll 4
            for (int i = 0; i < 100; i++) mx = fmaxf(mx, sw[i]);
            float ev = (tid < 100) ? __expf(sw[tid] - mx) : 0.f;
            __syncthreads();
            if (tid < 100) sw[tid] = ev;
            __syncthreads();
            float sum = 0.f;
#pragma unroll 4
            for (int i = 0; i < 100; i++) sum += sw[i];
            float inv = 1.f / sum;
#pragma unroll
            for (int kk = 0; kk < 4; kk++) {
                int k = kk * 256 + tid;
                const float* eT = &g_encT[b][k][0];
                float acc = 0.f;
#pragma unroll
                for (int s4 = 0; s4 < 100; s4 += 4) {
                    float4 e4 = *(const float4*)(eT + s4);
                    acc += sw[s4] * e4.x + sw[s4 + 1] * e4.y
                         + sw[s4 + 2] * e4.z + sw[s4 + 3] * e4.w;
                }
                g_ctxs[t][b][k] = acc * inv;
            }
        }
        gridbar();
        // ---- phase D: gate GEMM over K=1536 (ctx 1024 | h 512), k-split 2 ----
        if (bid < 128) {
            int kh = bid >> 6;
            int u0 = (bid & 63) * 8;
            float acc[4][4];
#pragma unroll
            for (int i = 0; i < 4; i++)
#pragma unroll
                for (int j = 0; j < 4; j++) acc[i][j] = 0.f;
            for (int c = 0; c < 6; c++) {
#pragma unroll
                for (int i = 0; i < 4; i++) {
                    int idx = tid * 4 + i;
                    int kgs = idx >> 8, r = (idx >> 3) & 31, q = idx & 7;
                    int k = kh * 768 + kgs * 192 + c * 32 + q * 4;
                    int grow = ((r >> 3) << 9) + u0 + (r & 7);
                    if (k < 1024) {
                        *(float4*)&Ws[kgs][r][q * 4] =
                            *(const float4*)(dWih + (size_t)grow * H3 + 512 + k);
                        *(float4*)&Xs[kgs][r][q * 4] = __ldcg((const float4*)&g_ctxs[t][r][k]);
                    } else {
                        *(float4*)&Ws[kgs][r][q * 4] =
                            *(const float4*)(dWhh + (size_t)grow * Hq + (k - 1024));
                        *(float4*)&Xs[kgs][r][q * 4] =
                            __ldcg((const float4*)&g_hd[slot][r][k - 1024]);
                    }
                }
                __syncthreads();
                mm4x4(Ws, Xs, kg, rx, bx, acc);
                __syncthreads();
            }
#pragma unroll
            for (int i = 0; i < 4; i++)
#pragma unroll
                for (int j = 0; j < 4; j++)
                    SAC(kg, rx + 8 * i, bx + 8 * j) = acc[i][j];
            __syncthreads();
#pragma unroll
            for (int i = 0; i < 4; i++) {
                int cell = i * 256 + tid;
                int r = cell >> 5, b = cell & 31;
                int gr = ((r >> 3) << 9) + u0 + (r & 7);
                g_gpart[kh][gr][b] = SAC(0, r, b) + SAC(1, r, b) + SAC(2, r, b) + SAC(3, r, b);
            }
        }
        gridbar();
        // ---- phase E: combine partials + LSTM update ----
        if (bid < 64) {
            int uj = tid >> 5, b = tid & 31;
            int u = (bid << 3) + uj;
            const float* Xp = g_Xdec + ((size_t)t * Bq + b) * G4;
            float gi = __ldcg(&g_gpart[0][u][b])        + __ldcg(&g_gpart[1][u][b])        + Xp[u];
            float gf = __ldcg(&g_gpart[0][512 + u][b])  + __ldcg(&g_gpart[1][512 + u][b])  + Xp[512 + u];
            float gg = __ldcg(&g_gpart[0][1024 + u][b]) + __ldcg(&g_gpart[1][1024 + u][b]) + Xp[1024 + u];
            float go = __ldcg(&g_gpart[0][1536 + u][b]) + __ldcg(&g_gpart[1][1536 + u][b]) + Xp[1536 + u];
            float c = c_s[uj][b];
            c = sigf(gf) * c + sigf(gi) * tanhf(gg);
            float h = sigf(go) * tanhf(c);
            c_s[uj][b] = c;
            g_hd[slot ^ 1][b][u] = h;
            g_decs[t][b][u] = h;
        }
        gridbar();
    }
}

// ---------------- classifier input pack ----------------
__global__ void k_pack() {
    int m = blockIdx.x;            // m = b*T + t
    int b = m / Tq, t = m % Tq;
    int tid = threadIdx.x;         // 128
    float4* dst = (float4*)(g_clsin + (size_t)m * 2048);
    dst[tid]       = ((const float4*)&g_temb[b][t][0])[tid];
    dst[128 + tid] = ((const float4*)&g_ctxs[t][b][0])[tid];
    dst[256 + tid] = ((const float4*)&g_ctxs[t][b][0])[128 + tid];
    dst[384 + tid] = ((const float4*)&g_decs[t][b][0])[tid];
}

// ---------------- host ----------------
extern "C" void kernel_launch(void* const* d_in, const int* in_sizes, int n_in,
                              void* d_out, int out_size) {
    (void)in_sizes; (void)n_in; (void)out_size;
    const int*   src       = (const int*)d_in[0];
    const int*   tgt       = (const int*)d_in[1];
    const float* src_emb   = (const float*)d_in[2];
    const float* tgt_emb   = (const float*)d_in[3];
    const float* eWih_f    = (const float*)d_in[4];
    const float* eWhh_f    = (const float*)d_in[5];
    const float* ebih_f    = (const float*)d_in[6];
    const float* ebhh_f    = (const float*)d_in[7];
    const float* eWih_b    = (const float*)d_in[8];
    const float* eWhh_b    = (const float*)d_in[9];
    const float* ebih_b    = (const float*)d_in[10];
    const float* ebhh_b    = (const float*)d_in[11];
    const float* dWih      = (const float*)d_in[12];
    const float* dWhh      = (const float*)d_in[13];
    const float* dbih      = (const float*)d_in[14];
    const float* dbhh      = (const float*)d_in[15];
    const float* att1_W    = (const float*)d_in[16];
    const float* att1_b    = (const float*)d_in[17];
    const float* att2_W    = (const float*)d_in[18];
    const float* cls1_W    = (const float*)d_in[20];
    const float* cls1_b    = (const float*)d_in[21];
    const float* cls2_W    = (const float*)d_in[22];
    const float* cls2_b    = (const float*)d_in[23];
    float* out = (float*)d_out;

    float *p_xsrc, *p_Xf, *p_Xb, *p_encout, *p_P, *p_temb_tb, *p_Xdec, *p_clsin, *p_hid;
    cudaGetSymbolAddress((void**)&p_xsrc, g_xsrc);
    cudaGetSymbolAddress((void**)&p_Xf, g_Xf);
    cudaGetSymbolAddress((void**)&p_Xb, g_Xb);
    cudaGetSymbolAddress((void**)&p_encout, g_encout);
    cudaGetSymbolAddress((void**)&p_P, g_P);
    cudaGetSymbolAddress((void**)&p_temb_tb, g_temb_tb);
    cudaGetSymbolAddress((void**)&p_Xdec, g_Xdec);
    cudaGetSymbolAddress((void**)&p_clsin, g_clsin);
    cudaGetSymbolAddress((void**)&p_hid, g_hid);

    k_gather_src<<<Sq * Bq, 128>>>(src, src_emb);
    k_gather_tgt<<<Bq * Tq, 128>>>(tgt, tgt_emb);

    // encoder input gates
    k_mma<<<dim3(25, 16), 256>>>(p_xsrc, Eq, eWih_f, Eq, ebih_f, ebhh_f,
                                 p_Xf, G4, Sq * Bq, G4, Eq, 0);
    k_mma<<<dim3(25, 16), 256>>>(p_xsrc, Eq, eWih_b, Eq, ebih_b, ebhh_b,
                                 p_Xb, G4, Sq * Bq, G4, Eq, 0);

    // persistent encoder (100 steps, 1 launch)
    k_enc_loop<<<NB, 256>>>(eWhh_f, eWhh_b);

    // attention layer-1 enc part (hoisted)
    k_mma<<<dim3(25, 12), 256>>>(p_encout, H2, att1_W, H3, att1_b, (const float*)nullptr,
                                 p_P, H3, Bq * Sq, H3, H2, 0);

    // decoder input gates (embedding part)
    k_mma<<<dim3(25, 16), 256>>>(p_temb_tb, Eq, dWih, H3, dbih, dbhh,
                                 p_Xdec, G4, Tq * Bq, G4, Eq, 0);

    // persistent decoder (100 steps, 1 launch)
    k_dec_loop<<<NB, 256>>>(att1_W, att2_W, dWih, dWhh);

    k_pack<<<Bq * Tq, 128>>>();

    // classifier
    k_mma<<<dim3(25, 8), 256>>>(p_clsin, 2048, cls1_W, 2048, cls1_b, (const float*)nullptr,
                                p_hid, H2, Bq * Tq, H2, 2048, 1);
    k_mma<<<dim3(25, 250), 256>>>(p_hid, H2, cls2_W, H2, cls2_b, (const float*)nullptr,
                                  out, VTq, Bq * Tq, VTq, H2, 0);
}